// round 15
// baseline (speedup 1.0000x reference)
#include <cuda_runtime.h>
#include <cstdint>
#include <cstddef>

#define SEQ   4096
#define BATCH 256
#define NS    16
#define MS    8
#define US    4
#define LCH   8           // chunk length
#define NCH   512         // chunks
#define GRP   16          // chunks per group
#define NGRP  32          // groups
#define GQ    448         // gain scalars per t: M(256)|N(64)|K(128)

typedef unsigned long long u64;

// ---------------- device scratch ----------------
__device__ __align__(16) float d_G[(size_t)SEQ * GQ];     // scalar gains per t
__device__ int d_tlast;                                   // last distinct gain index
__device__ __align__(16) float d_Phi[NCH * 256];
__device__ __align__(16) float d_Psi[NGRP * 256];
__device__ __align__(16) float d_V  [(size_t)NCH  * BATCH * NS];
__device__ __align__(16) float d_GV [(size_t)NGRP * BATCH * NS];
__device__ __align__(16) float d_GS [(size_t)NGRP * BATCH * NS];
__device__ __align__(16) float d_Sst[(size_t)NCH  * BATCH * NS];
// column-packed per-step states: [(chunk*LCH+step)*8 + q][batch] u64 = (x_{2q},x_{2q+1})
__device__ __align__(16) u64 d_Vt[(size_t)NCH * LCH * 8 * BATCH];

// ---------------- grid barrier (epoch-based, replay-safe) ----------------
__device__ unsigned int g_cnt = 0;
__device__ volatile unsigned int g_epoch = 0;

__device__ __forceinline__ void gsync(unsigned int target)
{
    __syncthreads();
    if (threadIdx.x == 0) {
        __threadfence();
        unsigned int prev = atomicAdd(&g_cnt, 1u);
        if (prev == gridDim.x - 1u) {
            atomicExch(&g_cnt, 0u);
            __threadfence();
            g_epoch = target;
        } else {
            while (g_epoch != target) __nanosleep(64);
        }
        __threadfence();
    }
    __syncthreads();
}

// ---------------- f32x2 helpers ----------------
__device__ __forceinline__ u64 ffma2(u64 a, u64 b, u64 c) {
    u64 d;
    asm("fma.rn.f32x2 %0, %1, %2, %3;" : "=l"(d) : "l"(a), "l"(b), "l"(c));
    return d;
}
__device__ __forceinline__ u64 fmul2(u64 a, u64 b) {
    u64 d;
    asm("mul.rn.f32x2 %0, %1, %2;" : "=l"(d) : "l"(a), "l"(b));
    return d;
}
__device__ __forceinline__ u64 pack2(float x, float y) {
    u64 r;
    asm("mov.b64 %0, {%1, %2};" : "=l"(r) : "f"(x), "f"(y));
    return r;
}
__device__ __forceinline__ void unpk2(u64 v, float& lo, float& hi) {
    asm("mov.b64 {%0, %1}, %2;" : "=f"(lo), "=f"(hi) : "l"(v));
}
__device__ __forceinline__ float hadd2(u64 v) {
    float lo, hi;
    unpk2(v, lo, hi);
    return lo + hi;
}

// =========================================================================
// Kernel 1: serial Riccati recursion (one block), scalar gain output
// =========================================================================
__global__ void __launch_bounds__(256) riccati_kernel(
    const float* __restrict__ A, const float* __restrict__ B,
    const float* __restrict__ C, const float* __restrict__ Q,
    const float* __restrict__ R)
{
    __shared__ float sA[256], sB[64], sC[128], sQ[256], sR[64];
    __shared__ float sCA[128], sCB[32], sCQ[128], sSR0[64];
    __shared__ float sP[256], sT1[256], sPp[256], sCT[128], sW[128], sK[128], sSm[64], sSi[64];

    const int tid = threadIdx.x;
    const int i  = tid >> 4;
    const int jc = tid & 15;

    sA[tid] = A[tid];
    sQ[tid] = Q[tid];
    if (tid < 64)  { sB[tid] = B[tid]; sR[tid] = R[tid]; }
    if (tid < 128) sC[tid] = C[tid];
    sP[tid] = (i == jc) ? 1.0f : 0.0f;   // P0 = I
    __syncthreads();

    if (tid < 128) {                      // CA = C*A, CQ = C*Q  (8x16)
        float a = 0.f, q = 0.f;
        int m = tid >> 4, jj = tid & 15;
        #pragma unroll
        for (int k = 0; k < 16; ++k) {
            a += sC[m * 16 + k] * sA[k * 16 + jj];
            q += sC[m * 16 + k] * sQ[k * 16 + jj];
        }
        sCA[tid] = a; sCQ[tid] = q;
    }
    if (tid < 32) {                       // CB = C*B  (8x4)
        float a = 0.f;
        #pragma unroll
        for (int k = 0; k < 16; ++k) a += sC[(tid >> 2) * 16 + k] * sB[k * 4 + (tid & 3)];
        sCB[tid] = a;
    }
    __syncthreads();
    if (tid < 64) {                       // SR0 = CQ*C^T + R (8x8)
        int m = tid >> 3, n = tid & 7;
        float s = sR[tid];
        #pragma unroll
        for (int k = 0; k < 16; ++k) s += sCQ[m * 16 + k] * sC[n * 16 + k];
        sSR0[tid] = s;
    }
    __syncthreads();

    int tconv = SEQ;
    for (int t = 1; t < SEQ; ++t) {
        // (1) T1 = A * P
        float a = 0.f;
        #pragma unroll
        for (int k = 0; k < 16; ++k) a += sA[i * 16 + k] * sP[k * 16 + jc];
        sT1[tid] = a;
        __syncthreads();
        // (2) Ppri = T1*A^T + Q (all)  ;  CT = C*T1 (tid<128)
        a = sQ[tid];
        #pragma unroll
        for (int k = 0; k < 16; ++k) a += sT1[i * 16 + k] * sA[jc * 16 + k];
        sPp[tid] = a;
        if (tid < 128) {
            int m = tid >> 4, jj = tid & 15;
            float w = 0.f;
            #pragma unroll
            for (int k = 0; k < 16; ++k) w += sC[m * 16 + k] * sT1[k * 16 + jj];
            sCT[tid] = w;
        }
        __syncthreads();
        // (3) W = CT*A^T + CQ (tid<128)  ;  S = CT*CA^T + SR0 (tid 128..191)
        if (tid < 128) {
            int m = tid >> 4, jj = tid & 15;
            float w = sCQ[tid];
            #pragma unroll
            for (int k = 0; k < 16; ++k) w += sCT[m * 16 + k] * sA[jj * 16 + k];
            sW[tid] = w;
        } else if (tid < 192) {
            int q = tid - 128, m = q >> 3, n = q & 7;
            float s = sSR0[q];
            #pragma unroll
            for (int k = 0; k < 16; ++k) s += sCT[m * 16 + k] * sCA[n * 16 + k];
            sSm[q] = s;
        }
        __syncthreads();
        // (4) Sinv: warp-synchronous Gauss-Jordan (8 lanes, SPD)
        if (tid < 8) {
            float row[16];
            #pragma unroll
            for (int c = 0; c < 8; ++c) { row[c] = sSm[tid * 8 + c]; row[c + 8] = (c == tid) ? 1.f : 0.f; }
            #pragma unroll
            for (int p = 0; p < 8; ++p) {
                float pv  = __shfl_sync(0xFFu, row[p], p, 8);
                float f   = row[p];
                float inv = 1.0f / pv;
                #pragma unroll
                for (int c = 0; c < 16; ++c) {
                    float pr = __shfl_sync(0xFFu, row[c], p, 8) * inv;
                    row[c] = (tid == p) ? pr : (row[c] - f * pr);
                }
            }
            #pragma unroll
            for (int c = 0; c < 8; ++c) sSi[tid * 8 + c] = row[c + 8];
        }
        __syncthreads();
        // (5) K = W^T * Sinv  (16x8)
        if (tid < 128) {
            int ii = tid >> 3, m = tid & 7;
            float kk = 0.f;
            #pragma unroll
            for (int n = 0; n < 8; ++n) kk += sW[n * 16 + ii] * sSi[n * 8 + m];
            sK[tid] = kk;
        }
        __syncthreads();
        // (6) outputs + Ppost + convergence
        {
            float mm = sA[tid];                         // M = A - K*CA
            #pragma unroll
            for (int m = 0; m < 8; ++m) mm -= sK[i * 8 + m] * sCA[m * 16 + jc];
            d_G[(size_t)t * GQ + tid] = mm;
        }
        if (tid < 64) {                                 // N = B - K*CB
            int ii = tid >> 2, u = tid & 3;
            float nn = sB[tid];
            #pragma unroll
            for (int m = 0; m < 8; ++m) nn -= sK[ii * 8 + m] * sCB[m * 4 + u];
            d_G[(size_t)t * GQ + 256 + tid] = nn;
        }
        if (tid < 128) d_G[(size_t)t * GQ + 320 + tid] = sK[tid];
        float pn = sPp[tid];                            // Ppost = Ppri - K*W
        #pragma unroll
        for (int m = 0; m < 8; ++m) pn -= sK[i * 8 + m] * sW[m * 16 + jc];
        int pred = fabsf(pn - sP[tid]) < 1e-5f;
        sP[tid] = pn;
        int conv = __syncthreads_and(pred);
        if (conv) { tconv = t + 1; break; }
    }
    __syncthreads();
    if (tid == 0) d_tlast = (tconv < SEQ) ? (tconv - 1) : (SEQ - 1);
}

// ---------------- 16-lane shuffle matvec with register-passed rows ----------
__device__ __forceinline__ float affine16r(float4 p0, float4 p1, float4 p2, float4 p3,
                                           float v, float s)
{
    float a = v;
    a += p0.x * __shfl_sync(0xFFFFFFFFu, s, 0, 16)  + p0.y * __shfl_sync(0xFFFFFFFFu, s, 1, 16)
       + p0.z * __shfl_sync(0xFFFFFFFFu, s, 2, 16)  + p0.w * __shfl_sync(0xFFFFFFFFu, s, 3, 16);
    a += p1.x * __shfl_sync(0xFFFFFFFFu, s, 4, 16)  + p1.y * __shfl_sync(0xFFFFFFFFu, s, 5, 16)
       + p1.z * __shfl_sync(0xFFFFFFFFu, s, 6, 16)  + p1.w * __shfl_sync(0xFFFFFFFFu, s, 7, 16);
    a += p2.x * __shfl_sync(0xFFFFFFFFu, s, 8, 16)  + p2.y * __shfl_sync(0xFFFFFFFFu, s, 9, 16)
       + p2.z * __shfl_sync(0xFFFFFFFFu, s, 10, 16) + p2.w * __shfl_sync(0xFFFFFFFFu, s, 11, 16);
    a += p3.x * __shfl_sync(0xFFFFFFFFu, s, 12, 16) + p3.y * __shfl_sync(0xFFFFFFFFu, s, 13, 16)
       + p3.z * __shfl_sync(0xFFFFFFFFu, s, 14, 16) + p3.w * __shfl_sync(0xFFFFFFFFu, s, 15, 16);
    return a;
}

// one column-packed affine step for one batch:
//   acc2_i = Σ_pairs N,K,M packed FMAs ; x_i = lo+hi
__device__ __forceinline__ void kstep_col(
    float nx[NS], const float* __restrict__ g,
    const u64 x[8], const u64 zz[4], const u64 uu[2])
{
    #pragma unroll
    for (int i = 0; i < NS; ++i) {
        const ulonglong2* gn = reinterpret_cast<const ulonglong2*>(g + 256 + i * 4);
        ulonglong2 nv = gn[0];
        u64 a = fmul2(nv.x, uu[0]);
        a = ffma2(nv.y, uu[1], a);
        const ulonglong2* gk = reinterpret_cast<const ulonglong2*>(g + 320 + i * 8);
        ulonglong2 k0 = gk[0], k1 = gk[1];
        a = ffma2(k0.x, zz[0], a); a = ffma2(k0.y, zz[1], a);
        a = ffma2(k1.x, zz[2], a); a = ffma2(k1.y, zz[3], a);
        const ulonglong2* gm = reinterpret_cast<const ulonglong2*>(g + i * 16);
        ulonglong2 m0 = gm[0], m1 = gm[1], m2 = gm[2], m3 = gm[3];
        a = ffma2(m0.x, x[0], a); a = ffma2(m0.y, x[1], a);
        a = ffma2(m1.x, x[2], a); a = ffma2(m1.y, x[3], a);
        a = ffma2(m2.x, x[4], a); a = ffma2(m2.y, x[5], a);
        a = ffma2(m3.x, x[6], a); a = ffma2(m3.y, x[7], a);
        nx[i] = hadd2(a);
    }
}

// =========================================================================
// Kernel 2: fused persistent kernel (column-packed f32x2, scalar gains)
// =========================================================================
__global__ void __launch_bounds__(128, 4) fused_kernel(
    const float* __restrict__ obs, const float* __restrict__ inp,
    const float* __restrict__ x0, float* __restrict__ out)
{
    __shared__ __align__(16) float sG[LCH][GQ];      // 14336 B scalar gains
    __shared__ __align__(16) float sPfx[LCH][256];   // 8192 B prefix matrices (scalar)
    __shared__ float sPh[2][256];                    // 2048 B psi ping-pong

    const int j   = blockIdx.x;
    const int tid = threadIdx.x;
    const int b0  = tid, b1 = tid + 128;
    const int t0  = j * LCH + 1;
    const int steps = (t0 + LCH <= SEQ) ? LCH : (SEQ - t0);

    const unsigned int E0 = g_epoch;     // per-thread; epoch can't advance
    const int tlast = d_tlast;           // until all blocks reach first gsync

    // ---------------- P1a: stage all LCH gain sets (clamped index) ----------
    #pragma unroll
    for (int s = 0; s < LCH; ++s) {
        int tt = t0 + s; if (tt > tlast) tt = tlast;
        if (tid < 112)
            reinterpret_cast<float4*>(sG[s])[tid] =
                __ldg(reinterpret_cast<const float4*>(&d_G[(size_t)tt * GQ]) + tid); // prior launch — __ldg legal
    }
    __syncthreads();

    // ---------------- P1b: prefix matrices Pfx_s = M_s ··· M_0 --------------
    {
        sPfx[0][tid]       = sG[0][tid];
        sPfx[0][tid + 128] = sG[0][tid + 128];
        __syncthreads();
        for (int s = 1; s < steps; ++s) {
            #pragma unroll
            for (int h = 0; h < 2; ++h) {
                int e = tid + h * 128, ii = e >> 4, jc = e & 15;
                float a = 0.f;
                #pragma unroll
                for (int k = 0; k < 16; ++k) a += sG[s][ii * 16 + k] * sPfx[s - 1][k * 16 + jc];
                sPfx[s][e] = a;
            }
            __syncthreads();
        }
        d_Phi[j * 256 + tid]       = sPfx[steps - 1][tid];
        d_Phi[j * 256 + tid + 128] = sPfx[steps - 1][tid + 128];
    }

    // ---------------- P1c: vpass (column-packed); store per-step v_t --------
    {
        u64 xa[8], xb[8];
        #pragma unroll
        for (int q = 0; q < 8; ++q) { xa[q] = 0ull; xb[q] = 0ull; }
        for (int s = 0; s < steps; ++s) {
            const int t = t0 + s;
            // z,u loads (column pairs are memory-natural: no packing)
            const ulonglong2* z0p = reinterpret_cast<const ulonglong2*>(obs + ((size_t)b0 * SEQ + t) * MS);
            const ulonglong2* z1p = reinterpret_cast<const ulonglong2*>(obs + ((size_t)b1 * SEQ + t) * MS);
            ulonglong2 za0 = __ldg(z0p), za1 = __ldg(z0p + 1);
            ulonglong2 zb0 = __ldg(z1p), zb1 = __ldg(z1p + 1);
            u64 zza[4] = { za0.x, za0.y, za1.x, za1.y };
            u64 zzb[4] = { zb0.x, zb0.y, zb1.x, zb1.y };
            ulonglong2 ua = __ldg(reinterpret_cast<const ulonglong2*>(inp + ((size_t)b0 * SEQ + t) * US));
            ulonglong2 ub = __ldg(reinterpret_cast<const ulonglong2*>(inp + ((size_t)b1 * SEQ + t) * US));
            u64 uua[2] = { ua.x, ua.y };
            u64 uub[2] = { ub.x, ub.y };
            float nxa[NS], nxb[NS];
            kstep_col(nxa, sG[s], xa, zza, uua);
            kstep_col(nxb, sG[s], xb, zzb, uub);
            #pragma unroll
            for (int q = 0; q < 8; ++q) {
                xa[q] = pack2(nxa[2 * q], nxa[2 * q + 1]);
                xb[q] = pack2(nxb[2 * q], nxb[2 * q + 1]);
            }
            u64* vb = &d_Vt[((size_t)(j * LCH + s) * 8) * BATCH];
            #pragma unroll
            for (int q = 0; q < 8; ++q) { vb[q * BATCH + b0] = xa[q]; vb[q * BATCH + b1] = xb[q]; }
        }
        // chunk-final v in scalar layout for the scan phases
        float la[NS], lb[NS];
        #pragma unroll
        for (int q = 0; q < 8; ++q) {
            unpk2(xa[q], la[2 * q], la[2 * q + 1]);
            unpk2(xb[q], lb[2 * q], lb[2 * q + 1]);
        }
        float4* v0 = reinterpret_cast<float4*>(&d_V[((size_t)j * BATCH + b0) * NS]);
        float4* v1 = reinterpret_cast<float4*>(&d_V[((size_t)j * BATCH + b1) * NS]);
        v0[0] = make_float4(la[0], la[1], la[2],  la[3]);
        v0[1] = make_float4(la[4], la[5], la[6],  la[7]);
        v0[2] = make_float4(la[8], la[9], la[10], la[11]);
        v0[3] = make_float4(la[12], la[13], la[14], la[15]);
        v1[0] = make_float4(lb[0], lb[1], lb[2],  lb[3]);
        v1[1] = make_float4(lb[4], lb[5], lb[6],  lb[7]);
        v1[2] = make_float4(lb[8], lb[9], lb[10], lb[11]);
        v1[3] = make_float4(lb[12], lb[13], lb[14], lb[15]);
    }
    if (j == 0) {       // out[b][0] = x0 for every batch
        const float4* xp = reinterpret_cast<const float4*>(x0);
        float4 x00 = __ldg(xp), x01 = __ldg(xp + 1), x02 = __ldg(xp + 2), x03 = __ldg(xp + 3);
        float4* o0 = reinterpret_cast<float4*>(out + (size_t)b0 * SEQ * NS);
        float4* o1 = reinterpret_cast<float4*>(out + (size_t)b1 * SEQ * NS);
        o0[0] = x00; o0[1] = x01; o0[2] = x02; o0[3] = x03;
        o1[0] = x00; o1[1] = x01; o1[2] = x02; o1[3] = x03;
    }

    gsync(E0 + 1);

    // ---------------- P2: psi (blocks 480..511 only) | gscanA (0..479) ------
    if (j >= NCH - NGRP) {
        const int g = j - (NCH - NGRP);
        sPh[0][tid]       = d_Phi[(g * GRP) * 256 + tid];
        sPh[0][tid + 128] = d_Phi[(g * GRP) * 256 + tid + 128];
        __syncthreads();
        int pp = 0;
        for (int c = 1; c < GRP; ++c) {
            const float* Ms = &d_Phi[(g * GRP + c) * 256];
            #pragma unroll
            for (int h = 0; h < 2; ++h) {
                int e = tid + h * 128, ii = e >> 4, jc = e & 15;
                float a = 0.f;
                #pragma unroll
                for (int k = 0; k < 16; ++k) a += Ms[ii * 16 + k] * sPh[pp][k * 16 + jc];
                sPh[pp ^ 1][e] = a;
            }
            __syncthreads();
            pp ^= 1;
        }
        d_Psi[g * 256 + tid]       = sPh[pp][tid];
        d_Psi[g * 256 + tid + 128] = sPh[pp][tid + 128];
    } else {
        const int i = tid & 15;
        const int ntask = (j < 64) ? 3 : 2;
        for (int r = 0; r < ntask; ++r) {
            const int T = (r == 0) ? j : ((r == 1) ? j + (NCH - NGRP) : 2 * (NCH - NGRP) + j);
            const int g = T >> 5, sub = T & 31;
            const int b = sub * 8 + (tid >> 4);
            float s = 0.f;
            int ch = g * GRP;
            float v = d_V[((size_t)ch * BATCH + b) * NS + i];
            const float4* pr = reinterpret_cast<const float4*>(&d_Phi[ch * 256 + i * 16]);
            float4 p0 = pr[0], p1 = pr[1], p2 = pr[2], p3 = pr[3];
            #pragma unroll
            for (int c = 0; c < GRP; ++c) {
                float vn = 0.f; float4 q0, q1, q2, q3;
                if (c < GRP - 1) {                              // prefetch next chunk
                    const int chn = ch + 1;
                    vn = d_V[((size_t)chn * BATCH + b) * NS + i];
                    const float4* qn = reinterpret_cast<const float4*>(&d_Phi[chn * 256 + i * 16]);
                    q0 = qn[0]; q1 = qn[1]; q2 = qn[2]; q3 = qn[3];
                }
                s = affine16r(p0, p1, p2, p3, v, s);
                v = vn; p0 = q0; p1 = q1; p2 = q2; p3 = q3; ++ch;
            }
            d_GV[((size_t)g * BATCH + b) * NS + i] = s;
        }
    }

    gsync(E0 + 2);

    // ---------------- P3: gscanB (blocks 0..31, serial over 32 groups) ------
    if (j < 32) {
        const int b = j * 8 + (tid >> 4);
        const int i = tid & 15;
        float s = __ldg(x0 + i);
        float v = d_GV[(size_t)b * NS + i];
        const float4* pr = reinterpret_cast<const float4*>(&d_Psi[i * 16]);
        float4 p0 = pr[0], p1 = pr[1], p2 = pr[2], p3 = pr[3];
        #pragma unroll
        for (int g = 0; g < NGRP; ++g) {
            float vn = 0.f; float4 q0, q1, q2, q3;
            if (g < NGRP - 1) {                                 // prefetch next group
                vn = d_GV[((size_t)(g + 1) * BATCH + b) * NS + i];
                const float4* qn = reinterpret_cast<const float4*>(&d_Psi[(g + 1) * 256 + i * 16]);
                q0 = qn[0]; q1 = qn[1]; q2 = qn[2]; q3 = qn[3];
            }
            d_GS[((size_t)g * BATCH + b) * NS + i] = s;
            s = affine16r(p0, p1, p2, p3, v, s);
            v = vn; p0 = q0; p1 = q1; p2 = q2; p3 = q3;
        }
    }

    gsync(E0 + 3);

    // ---------------- P4a: gscanC (all blocks, 2 tasks, prefetched) ---------
    {
        const int i = tid & 15;
        #pragma unroll
        for (int rep = 0; rep < 2; ++rep) {
            const int T = j + rep * NCH;
            const int g = T >> 5, sub = T & 31;
            const int b = sub * 8 + (tid >> 4);
            float s = d_GS[((size_t)g * BATCH + b) * NS + i];
            int ch = g * GRP;
            float v = d_V[((size_t)ch * BATCH + b) * NS + i];
            const float4* pr = reinterpret_cast<const float4*>(&d_Phi[ch * 256 + i * 16]);
            float4 p0 = pr[0], p1 = pr[1], p2 = pr[2], p3 = pr[3];
            #pragma unroll
            for (int c = 0; c < GRP; ++c) {
                float vn = 0.f; float4 q0, q1, q2, q3;
                if (c < GRP - 1) {
                    const int chn = ch + 1;
                    vn = d_V[((size_t)chn * BATCH + b) * NS + i];
                    const float4* qn = reinterpret_cast<const float4*>(&d_Phi[chn * 256 + i * 16]);
                    q0 = qn[0]; q1 = qn[1]; q2 = qn[2]; q3 = qn[3];
                }
                d_Sst[((size_t)ch * BATCH + b) * NS + i] = s;
                s = affine16r(p0, p1, p2, p3, v, s);
                v = vn; p0 = q0; p1 = q1; p2 = q2; p3 = q3; ++ch;
            }
        }
    }

    gsync(E0 + 4);

    // ---------------- P4b: outpass — out[t] = v_t + Pfx_s · s_j -------------
    {
        u64 sa[8], sb[8];
        {   // s_j column pairs are memory-natural from d_Sst
            const ulonglong2* s0 = reinterpret_cast<const ulonglong2*>(&d_Sst[((size_t)j * BATCH + b0) * NS]);
            const ulonglong2* s1 = reinterpret_cast<const ulonglong2*>(&d_Sst[((size_t)j * BATCH + b1) * NS]);
            #pragma unroll
            for (int q = 0; q < 4; ++q) {
                ulonglong2 w0 = s0[q]; sa[2 * q] = w0.x; sa[2 * q + 1] = w0.y;
                ulonglong2 w1 = s1[q]; sb[2 * q] = w1.x; sb[2 * q + 1] = w1.y;
            }
        }
        for (int s = 0; s < steps; ++s) {
            const int t = t0 + s;
            u64 va[8], vb2[8];
            {
                const u64* vb = &d_Vt[((size_t)(j * LCH + s) * 8) * BATCH];
                #pragma unroll
                for (int q = 0; q < 8; ++q) { va[q] = vb[q * BATCH + b0]; vb2[q] = vb[q * BATCH + b1]; }
            }
            float ra[NS], rb[NS];
            #pragma unroll
            for (int i = 0; i < NS; ++i) {
                const ulonglong2* P = reinterpret_cast<const ulonglong2*>(sPfx[s] + i * 16);
                ulonglong2 p0 = P[0], p1 = P[1], p2 = P[2], p3 = P[3];
                u64 a0 = fmul2(p0.x, sa[0]);
                a0 = ffma2(p0.y, sa[1], a0);
                a0 = ffma2(p1.x, sa[2], a0); a0 = ffma2(p1.y, sa[3], a0);
                a0 = ffma2(p2.x, sa[4], a0); a0 = ffma2(p2.y, sa[5], a0);
                a0 = ffma2(p3.x, sa[6], a0); a0 = ffma2(p3.y, sa[7], a0);
                u64 a1 = fmul2(p0.x, sb[0]);
                a1 = ffma2(p0.y, sb[1], a1);
                a1 = ffma2(p1.x, sb[2], a1); a1 = ffma2(p1.y, sb[3], a1);
                a1 = ffma2(p2.x, sb[4], a1); a1 = ffma2(p2.y, sb[5], a1);
                a1 = ffma2(p3.x, sb[6], a1); a1 = ffma2(p3.y, sb[7], a1);
                float vlo, vhi;
                unpk2(va[i >> 1], vlo, vhi);
                ra[i] = ((i & 1) ? vhi : vlo) + hadd2(a0);
                unpk2(vb2[i >> 1], vlo, vhi);
                rb[i] = ((i & 1) ? vhi : vlo) + hadd2(a1);
            }
            float4* o0 = reinterpret_cast<float4*>(out + ((size_t)b0 * SEQ + t) * NS);
            float4* o1 = reinterpret_cast<float4*>(out + ((size_t)b1 * SEQ + t) * NS);
            o0[0] = make_float4(ra[0],  ra[1],  ra[2],  ra[3]);
            o0[1] = make_float4(ra[4],  ra[5],  ra[6],  ra[7]);
            o0[2] = make_float4(ra[8],  ra[9],  ra[10], ra[11]);
            o0[3] = make_float4(ra[12], ra[13], ra[14], ra[15]);
            o1[0] = make_float4(rb[0],  rb[1],  rb[2],  rb[3]);
            o1[1] = make_float4(rb[4],  rb[5],  rb[6],  rb[7]);
            o1[2] = make_float4(rb[8],  rb[9],  rb[10], rb[11]);
            o1[3] = make_float4(rb[12], rb[13], rb[14], rb[15]);
        }
    }
}

// =========================================================================
extern "C" void kernel_launch(void* const* d_in, const int* in_sizes, int n_in,
                              void* d_out, int out_size)
{
    (void)in_sizes; (void)n_in; (void)out_size;
    const float* obs = (const float*)d_in[0];
    const float* inp = (const float*)d_in[1];
    const float* A   = (const float*)d_in[2];
    const float* B   = (const float*)d_in[3];
    const float* C   = (const float*)d_in[4];
    const float* Q   = (const float*)d_in[5];
    const float* R   = (const float*)d_in[6];
    const float* x0  = (const float*)d_in[7];
    float* out = (float*)d_out;

    riccati_kernel<<<1, 256>>>(A, B, C, Q, R);
    fused_kernel<<<NCH, 128>>>(obs, inp, x0, out);
}

// round 16
// speedup vs baseline: 1.0123x; 1.0123x over previous
#include <cuda_runtime.h>
#include <cstdint>
#include <cstddef>

#define SEQ   4096
#define BATCH 256
#define NS    16
#define MS    8
#define US    4
#define LCH   8           // chunk length
#define NCH   512         // chunks
#define GRP   16          // chunks per group
#define NGRP  32          // groups
#define GQ    448         // gain scalars per t: M(256)|N(64)|K(128)

typedef unsigned long long u64;

// ---------------- device scratch ----------------
__device__ __align__(16) float d_G[(size_t)SEQ * GQ];     // scalar gains per t
__device__ int d_tlast;                                   // last distinct gain index
__device__ __align__(16) float d_Phi[NCH * 256];
__device__ __align__(16) float d_Psi[NGRP * 256];
__device__ __align__(16) float d_V  [(size_t)NCH  * BATCH * NS];
__device__ __align__(16) float d_GV [(size_t)NGRP * BATCH * NS];
__device__ __align__(16) float d_GS [(size_t)NGRP * BATCH * NS];
__device__ __align__(16) float d_Sst[(size_t)NCH  * BATCH * NS];
// batch-pair packed per-step states (r12 layout): [(chunk*LCH+step)*16+q][tid(128)]
__device__ __align__(16) u64 d_Vt[(size_t)NCH * LCH * NS * 128];

// ---------------- grid barrier (epoch-based, replay-safe) ----------------
__device__ unsigned int g_cnt = 0;
__device__ volatile unsigned int g_epoch = 0;

__device__ __forceinline__ void gsync(unsigned int target)
{
    __syncthreads();
    if (threadIdx.x == 0) {
        __threadfence();
        unsigned int prev = atomicAdd(&g_cnt, 1u);
        if (prev == gridDim.x - 1u) {
            atomicExch(&g_cnt, 0u);
            __threadfence();
            g_epoch = target;
        } else {
            while (g_epoch != target) __nanosleep(64);
        }
        __threadfence();
    }
    __syncthreads();
}

// ---------------- f32x2 helpers ----------------
__device__ __forceinline__ u64 ffma2(u64 a, u64 b, u64 c) {
    u64 d;
    asm("fma.rn.f32x2 %0, %1, %2, %3;" : "=l"(d) : "l"(a), "l"(b), "l"(c));
    return d;
}
__device__ __forceinline__ u64 fmul2(u64 a, u64 b) {
    u64 d;
    asm("mul.rn.f32x2 %0, %1, %2;" : "=l"(d) : "l"(a), "l"(b));
    return d;
}
__device__ __forceinline__ u64 pack2(float x, float y) {
    u64 r;
    asm("mov.b64 %0, {%1, %2};" : "=l"(r) : "f"(x), "f"(y));
    return r;
}
__device__ __forceinline__ void unpk2(u64 v, float& lo, float& hi) {
    asm("mov.b64 {%0, %1}, %2;" : "=f"(lo), "=f"(hi) : "l"(v));
}
__device__ __forceinline__ float hadd2(u64 v) {
    float lo, hi;
    unpk2(v, lo, hi);
    return lo + hi;
}

// =========================================================================
// Kernel 1: serial Riccati recursion (one block), scalar gain output
// =========================================================================
__global__ void __launch_bounds__(256) riccati_kernel(
    const float* __restrict__ A, const float* __restrict__ B,
    const float* __restrict__ C, const float* __restrict__ Q,
    const float* __restrict__ R)
{
    __shared__ float sA[256], sB[64], sC[128], sQ[256], sR[64];
    __shared__ float sCA[128], sCB[32], sCQ[128], sSR0[64];
    __shared__ float sP[256], sT1[256], sPp[256], sCT[128], sW[128], sK[128], sSm[64], sSi[64];

    const int tid = threadIdx.x;
    const int i  = tid >> 4;
    const int jc = tid & 15;

    sA[tid] = A[tid];
    sQ[tid] = Q[tid];
    if (tid < 64)  { sB[tid] = B[tid]; sR[tid] = R[tid]; }
    if (tid < 128) sC[tid] = C[tid];
    sP[tid] = (i == jc) ? 1.0f : 0.0f;   // P0 = I
    __syncthreads();

    if (tid < 128) {                      // CA = C*A, CQ = C*Q  (8x16)
        float a = 0.f, q = 0.f;
        int m = tid >> 4, jj = tid & 15;
        #pragma unroll
        for (int k = 0; k < 16; ++k) {
            a += sC[m * 16 + k] * sA[k * 16 + jj];
            q += sC[m * 16 + k] * sQ[k * 16 + jj];
        }
        sCA[tid] = a; sCQ[tid] = q;
    }
    if (tid < 32) {                       // CB = C*B  (8x4)
        float a = 0.f;
        #pragma unroll
        for (int k = 0; k < 16; ++k) a += sC[(tid >> 2) * 16 + k] * sB[k * 4 + (tid & 3)];
        sCB[tid] = a;
    }
    __syncthreads();
    if (tid < 64) {                       // SR0 = CQ*C^T + R (8x8)
        int m = tid >> 3, n = tid & 7;
        float s = sR[tid];
        #pragma unroll
        for (int k = 0; k < 16; ++k) s += sCQ[m * 16 + k] * sC[n * 16 + k];
        sSR0[tid] = s;
    }
    __syncthreads();

    int tconv = SEQ;
    for (int t = 1; t < SEQ; ++t) {
        // (1) T1 = A * P
        float a = 0.f;
        #pragma unroll
        for (int k = 0; k < 16; ++k) a += sA[i * 16 + k] * sP[k * 16 + jc];
        sT1[tid] = a;
        __syncthreads();
        // (2) Ppri = T1*A^T + Q (all)  ;  CT = C*T1 (tid<128)
        a = sQ[tid];
        #pragma unroll
        for (int k = 0; k < 16; ++k) a += sT1[i * 16 + k] * sA[jc * 16 + k];
        sPp[tid] = a;
        if (tid < 128) {
            int m = tid >> 4, jj = tid & 15;
            float w = 0.f;
            #pragma unroll
            for (int k = 0; k < 16; ++k) w += sC[m * 16 + k] * sT1[k * 16 + jj];
            sCT[tid] = w;
        }
        __syncthreads();
        // (3) W = CT*A^T + CQ (tid<128)  ;  S = CT*CA^T + SR0 (tid 128..191)
        if (tid < 128) {
            int m = tid >> 4, jj = tid & 15;
            float w = sCQ[tid];
            #pragma unroll
            for (int k = 0; k < 16; ++k) w += sCT[m * 16 + k] * sA[jj * 16 + k];
            sW[tid] = w;
        } else if (tid < 192) {
            int q = tid - 128, m = q >> 3, n = q & 7;
            float s = sSR0[q];
            #pragma unroll
            for (int k = 0; k < 16; ++k) s += sCT[m * 16 + k] * sCA[n * 16 + k];
            sSm[q] = s;
        }
        __syncthreads();
        // (4) Sinv: warp-synchronous Gauss-Jordan (8 lanes, SPD)
        if (tid < 8) {
            float row[16];
            #pragma unroll
            for (int c = 0; c < 8; ++c) { row[c] = sSm[tid * 8 + c]; row[c + 8] = (c == tid) ? 1.f : 0.f; }
            #pragma unroll
            for (int p = 0; p < 8; ++p) {
                float pv  = __shfl_sync(0xFFu, row[p], p, 8);
                float f   = row[p];
                float inv = 1.0f / pv;
                #pragma unroll
                for (int c = 0; c < 16; ++c) {
                    float pr = __shfl_sync(0xFFu, row[c], p, 8) * inv;
                    row[c] = (tid == p) ? pr : (row[c] - f * pr);
                }
            }
            #pragma unroll
            for (int c = 0; c < 8; ++c) sSi[tid * 8 + c] = row[c + 8];
        }
        __syncthreads();
        // (5) K = W^T * Sinv  (16x8)
        if (tid < 128) {
            int ii = tid >> 3, m = tid & 7;
            float kk = 0.f;
            #pragma unroll
            for (int n = 0; n < 8; ++n) kk += sW[n * 16 + ii] * sSi[n * 8 + m];
            sK[tid] = kk;
        }
        __syncthreads();
        // (6) outputs + Ppost + convergence
        {
            float mm = sA[tid];                         // M = A - K*CA
            #pragma unroll
            for (int m = 0; m < 8; ++m) mm -= sK[i * 8 + m] * sCA[m * 16 + jc];
            d_G[(size_t)t * GQ + tid] = mm;
        }
        if (tid < 64) {                                 // N = B - K*CB
            int ii = tid >> 2, u = tid & 3;
            float nn = sB[tid];
            #pragma unroll
            for (int m = 0; m < 8; ++m) nn -= sK[ii * 8 + m] * sCB[m * 4 + u];
            d_G[(size_t)t * GQ + 256 + tid] = nn;
        }
        if (tid < 128) d_G[(size_t)t * GQ + 320 + tid] = sK[tid];
        float pn = sPp[tid];                            // Ppost = Ppri - K*W
        #pragma unroll
        for (int m = 0; m < 8; ++m) pn -= sK[i * 8 + m] * sW[m * 16 + jc];
        int pred = fabsf(pn - sP[tid]) < 1e-5f;
        sP[tid] = pn;
        int conv = __syncthreads_and(pred);
        if (conv) { tconv = t + 1; break; }
    }
    __syncthreads();
    if (tid == 0) d_tlast = (tconv < SEQ) ? (tconv - 1) : (SEQ - 1);
}

// ---------------- 16-lane shuffle matvec with register-passed rows ----------
__device__ __forceinline__ float affine16r(float4 p0, float4 p1, float4 p2, float4 p3,
                                           float v, float s)
{
    float a = v;
    a += p0.x * __shfl_sync(0xFFFFFFFFu, s, 0, 16)  + p0.y * __shfl_sync(0xFFFFFFFFu, s, 1, 16)
       + p0.z * __shfl_sync(0xFFFFFFFFu, s, 2, 16)  + p0.w * __shfl_sync(0xFFFFFFFFu, s, 3, 16);
    a += p1.x * __shfl_sync(0xFFFFFFFFu, s, 4, 16)  + p1.y * __shfl_sync(0xFFFFFFFFu, s, 5, 16)
       + p1.z * __shfl_sync(0xFFFFFFFFu, s, 6, 16)  + p1.w * __shfl_sync(0xFFFFFFFFu, s, 7, 16);
    a += p2.x * __shfl_sync(0xFFFFFFFFu, s, 8, 16)  + p2.y * __shfl_sync(0xFFFFFFFFu, s, 9, 16)
       + p2.z * __shfl_sync(0xFFFFFFFFu, s, 10, 16) + p2.w * __shfl_sync(0xFFFFFFFFu, s, 11, 16);
    a += p3.x * __shfl_sync(0xFFFFFFFFu, s, 12, 16) + p3.y * __shfl_sync(0xFFFFFFFFu, s, 13, 16)
       + p3.z * __shfl_sync(0xFFFFFFFFu, s, 14, 16) + p3.w * __shfl_sync(0xFFFFFFFFu, s, 15, 16);
    return a;
}

// column-packed affine step for one batch (gains scalar in smem):
//   acc2_i = Σ column-pair FMAs ; nx_i = lo+hi
__device__ __forceinline__ void kstep_col(
    float nx[NS], const float* __restrict__ g,
    const u64 x[8], const u64 zz[4], const u64 uu[2])
{
    #pragma unroll
    for (int i = 0; i < NS; ++i) {
        const ulonglong2* gn = reinterpret_cast<const ulonglong2*>(g + 256 + i * 4);
        ulonglong2 nv = gn[0];
        u64 a = fmul2(nv.x, uu[0]);
        a = ffma2(nv.y, uu[1], a);
        const ulonglong2* gk = reinterpret_cast<const ulonglong2*>(g + 320 + i * 8);
        ulonglong2 k0 = gk[0], k1 = gk[1];
        a = ffma2(k0.x, zz[0], a); a = ffma2(k0.y, zz[1], a);
        a = ffma2(k1.x, zz[2], a); a = ffma2(k1.y, zz[3], a);
        const ulonglong2* gm = reinterpret_cast<const ulonglong2*>(g + i * 16);
        ulonglong2 m0 = gm[0], m1 = gm[1], m2 = gm[2], m3 = gm[3];
        a = ffma2(m0.x, x[0], a); a = ffma2(m0.y, x[1], a);
        a = ffma2(m1.x, x[2], a); a = ffma2(m1.y, x[3], a);
        a = ffma2(m2.x, x[4], a); a = ffma2(m2.y, x[5], a);
        a = ffma2(m3.x, x[6], a); a = ffma2(m3.y, x[7], a);
        nx[i] = hadd2(a);
    }
}

// =========================================================================
// Kernel 2: fused persistent kernel
//   = r12 structure; ONLY vpass switched to scalar-gain column packing.
//   d_Vt layout, d_V, scans, and outpass are byte-identical to r12.
// =========================================================================
__global__ void __launch_bounds__(128, 4) fused_kernel(
    const float* __restrict__ obs, const float* __restrict__ inp,
    const float* __restrict__ x0, float* __restrict__ out)
{
    __shared__ __align__(16) float sG[LCH][GQ];      // 14336 B scalar gains
    __shared__ __align__(16) u64 sPfx[LCH][256];     // 16384 B prefix matrices (dup pairs)
    __shared__ float sPh[2][256];                    // 2048 B psi ping-pong

    const int j   = blockIdx.x;
    const int tid = threadIdx.x;
    const int b0  = tid, b1 = tid + 128;
    const int t0  = j * LCH + 1;
    const int steps = (t0 + LCH <= SEQ) ? LCH : (SEQ - t0);

    const unsigned int E0 = g_epoch;     // per-thread; epoch can't advance
    const int tlast = d_tlast;           // until all blocks reach first gsync

    // ---------------- P1a: stage all LCH gain sets (clamped index) ----------
    #pragma unroll
    for (int s = 0; s < LCH; ++s) {
        int tt = t0 + s; if (tt > tlast) tt = tlast;
        if (tid < 112)
            reinterpret_cast<float4*>(sG[s])[tid] =
                __ldg(reinterpret_cast<const float4*>(&d_G[(size_t)tt * GQ]) + tid); // prior launch — __ldg legal
    }
    __syncthreads();

    // ---------------- P1b: prefix matrices Pfx_s = M_s ··· M_0 (dup out) ----
    {
        sPfx[0][tid]       = pack2(sG[0][tid], sG[0][tid]);
        sPfx[0][tid + 128] = pack2(sG[0][tid + 128], sG[0][tid + 128]);
        __syncthreads();
        for (int s = 1; s < steps; ++s) {
            const float* Pp = reinterpret_cast<const float*>(sPfx[s - 1]);
            #pragma unroll
            for (int h = 0; h < 2; ++h) {
                int e = tid + h * 128, ii = e >> 4, jc = e & 15;
                float a = 0.f;
                #pragma unroll
                for (int k = 0; k < 16; ++k) a += sG[s][ii * 16 + k] * Pp[2 * (k * 16 + jc)];
                sPfx[s][e] = pack2(a, a);
            }
            __syncthreads();
        }
        const float* Pl = reinterpret_cast<const float*>(sPfx[steps - 1]);
        d_Phi[j * 256 + tid]       = Pl[2 * tid];
        d_Phi[j * 256 + tid + 128] = Pl[2 * (tid + 128)];
    }

    // ---------------- P1c: vpass (column-packed), d_Vt in r12 layout --------
    {
        u64 xa[8], xb[8];
        #pragma unroll
        for (int q = 0; q < 8; ++q) { xa[q] = 0ull; xb[q] = 0ull; }
        float nxa[NS], nxb[NS];
        #pragma unroll
        for (int q = 0; q < NS; ++q) { nxa[q] = 0.f; nxb[q] = 0.f; }
        for (int s = 0; s < steps; ++s) {
            const int t = t0 + s;
            // z,u loads: column pairs are memory-natural (no packing)
            const ulonglong2* z0p = reinterpret_cast<const ulonglong2*>(obs + ((size_t)b0 * SEQ + t) * MS);
            const ulonglong2* z1p = reinterpret_cast<const ulonglong2*>(obs + ((size_t)b1 * SEQ + t) * MS);
            ulonglong2 za0 = __ldg(z0p), za1 = __ldg(z0p + 1);
            ulonglong2 zb0 = __ldg(z1p), zb1 = __ldg(z1p + 1);
            u64 zza[4] = { za0.x, za0.y, za1.x, za1.y };
            u64 zzb[4] = { zb0.x, zb0.y, zb1.x, zb1.y };
            ulonglong2 ua = __ldg(reinterpret_cast<const ulonglong2*>(inp + ((size_t)b0 * SEQ + t) * US));
            ulonglong2 ub = __ldg(reinterpret_cast<const ulonglong2*>(inp + ((size_t)b1 * SEQ + t) * US));
            u64 uua[2] = { ua.x, ua.y };
            u64 uub[2] = { ub.x, ub.y };
            kstep_col(nxa, sG[s], xa, zza, uua);
            kstep_col(nxb, sG[s], xb, zzb, uub);
            #pragma unroll
            for (int q = 0; q < 8; ++q) {
                xa[q] = pack2(nxa[2 * q], nxa[2 * q + 1]);
                xb[q] = pack2(nxb[2 * q], nxb[2 * q + 1]);
            }
            // d_Vt store: r12 batch-pair layout
            u64* vb = &d_Vt[((size_t)(j * LCH + s) * NS) * 128 + tid];
            #pragma unroll
            for (int q = 0; q < NS; ++q) vb[q * 128] = pack2(nxa[q], nxb[q]);
        }
        float4* v0 = reinterpret_cast<float4*>(&d_V[((size_t)j * BATCH + b0) * NS]);
        float4* v1 = reinterpret_cast<float4*>(&d_V[((size_t)j * BATCH + b1) * NS]);
        v0[0] = make_float4(nxa[0], nxa[1], nxa[2],  nxa[3]);
        v0[1] = make_float4(nxa[4], nxa[5], nxa[6],  nxa[7]);
        v0[2] = make_float4(nxa[8], nxa[9], nxa[10], nxa[11]);
        v0[3] = make_float4(nxa[12], nxa[13], nxa[14], nxa[15]);
        v1[0] = make_float4(nxb[0], nxb[1], nxb[2],  nxb[3]);
        v1[1] = make_float4(nxb[4], nxb[5], nxb[6],  nxb[7]);
        v1[2] = make_float4(nxb[8], nxb[9], nxb[10], nxb[11]);
        v1[3] = make_float4(nxb[12], nxb[13], nxb[14], nxb[15]);
    }
    if (j == 0) {       // out[b][0] = x0 for every batch
        const float4* xp = reinterpret_cast<const float4*>(x0);
        float4 x00 = __ldg(xp), x01 = __ldg(xp + 1), x02 = __ldg(xp + 2), x03 = __ldg(xp + 3);
        float4* o0 = reinterpret_cast<float4*>(out + (size_t)b0 * SEQ * NS);
        float4* o1 = reinterpret_cast<float4*>(out + (size_t)b1 * SEQ * NS);
        o0[0] = x00; o0[1] = x01; o0[2] = x02; o0[3] = x03;
        o1[0] = x00; o1[1] = x01; o1[2] = x02; o1[3] = x03;
    }

    gsync(E0 + 1);

    // ---------------- P2: psi (blocks 480..511 only) | gscanA (0..479) ------
    if (j >= NCH - NGRP) {
        const int g = j - (NCH - NGRP);
        sPh[0][tid]       = d_Phi[(g * GRP) * 256 + tid];
        sPh[0][tid + 128] = d_Phi[(g * GRP) * 256 + tid + 128];
        __syncthreads();
        int pp = 0;
        for (int c = 1; c < GRP; ++c) {
            const float* Ms = &d_Phi[(g * GRP + c) * 256];
            #pragma unroll
            for (int h = 0; h < 2; ++h) {
                int e = tid + h * 128, ii = e >> 4, jc = e & 15;
                float a = 0.f;
                #pragma unroll
                for (int k = 0; k < 16; ++k) a += Ms[ii * 16 + k] * sPh[pp][k * 16 + jc];
                sPh[pp ^ 1][e] = a;
            }
            __syncthreads();
            pp ^= 1;
        }
        d_Psi[g * 256 + tid]       = sPh[pp][tid];
        d_Psi[g * 256 + tid + 128] = sPh[pp][tid + 128];
    } else {
        const int i = tid & 15;
        const int ntask = (j < 64) ? 3 : 2;
        for (int r = 0; r < ntask; ++r) {
            const int T = (r == 0) ? j : ((r == 1) ? j + (NCH - NGRP) : 2 * (NCH - NGRP) + j);
            const int g = T >> 5, sub = T & 31;
            const int b = sub * 8 + (tid >> 4);
            float s = 0.f;
            int ch = g * GRP;
            float v = d_V[((size_t)ch * BATCH + b) * NS + i];
            const float4* pr = reinterpret_cast<const float4*>(&d_Phi[ch * 256 + i * 16]);
            float4 p0 = pr[0], p1 = pr[1], p2 = pr[2], p3 = pr[3];
            #pragma unroll
            for (int c = 0; c < GRP; ++c) {
                float vn = 0.f; float4 q0, q1, q2, q3;
                if (c < GRP - 1) {                              // prefetch next chunk
                    const int chn = ch + 1;
                    vn = d_V[((size_t)chn * BATCH + b) * NS + i];
                    const float4* qn = reinterpret_cast<const float4*>(&d_Phi[chn * 256 + i * 16]);
                    q0 = qn[0]; q1 = qn[1]; q2 = qn[2]; q3 = qn[3];
                }
                s = affine16r(p0, p1, p2, p3, v, s);
                v = vn; p0 = q0; p1 = q1; p2 = q2; p3 = q3; ++ch;
            }
            d_GV[((size_t)g * BATCH + b) * NS + i] = s;
        }
    }

    gsync(E0 + 2);

    // ---------------- P3: gscanB (blocks 0..31, serial over 32 groups) ------
    if (j < 32) {
        const int b = j * 8 + (tid >> 4);
        const int i = tid & 15;
        float s = __ldg(x0 + i);
        float v = d_GV[(size_t)b * NS + i];
        const float4* pr = reinterpret_cast<const float4*>(&d_Psi[i * 16]);
        float4 p0 = pr[0], p1 = pr[1], p2 = pr[2], p3 = pr[3];
        #pragma unroll
        for (int g = 0; g < NGRP; ++g) {
            float vn = 0.f; float4 q0, q1, q2, q3;
            if (g < NGRP - 1) {                                 // prefetch next group
                vn = d_GV[((size_t)(g + 1) * BATCH + b) * NS + i];
                const float4* qn = reinterpret_cast<const float4*>(&d_Psi[(g + 1) * 256 + i * 16]);
                q0 = qn[0]; q1 = qn[1]; q2 = qn[2]; q3 = qn[3];
            }
            d_GS[((size_t)g * BATCH + b) * NS + i] = s;
            s = affine16r(p0, p1, p2, p3, v, s);
            v = vn; p0 = q0; p1 = q1; p2 = q2; p3 = q3;
        }
    }

    gsync(E0 + 3);

    // ---------------- P4a: gscanC (all blocks, 2 tasks, prefetched) ---------
    {
        const int i = tid & 15;
        #pragma unroll
        for (int rep = 0; rep < 2; ++rep) {
            const int T = j + rep * NCH;
            const int g = T >> 5, sub = T & 31;
            const int b = sub * 8 + (tid >> 4);
            float s = d_GS[((size_t)g * BATCH + b) * NS + i];
            int ch = g * GRP;
            float v = d_V[((size_t)ch * BATCH + b) * NS + i];
            const float4* pr = reinterpret_cast<const float4*>(&d_Phi[ch * 256 + i * 16]);
            float4 p0 = pr[0], p1 = pr[1], p2 = pr[2], p3 = pr[3];
            #pragma unroll
            for (int c = 0; c < GRP; ++c) {
                float vn = 0.f; float4 q0, q1, q2, q3;
                if (c < GRP - 1) {
                    const int chn = ch + 1;
                    vn = d_V[((size_t)chn * BATCH + b) * NS + i];
                    const float4* qn = reinterpret_cast<const float4*>(&d_Phi[chn * 256 + i * 16]);
                    q0 = qn[0]; q1 = qn[1]; q2 = qn[2]; q3 = qn[3];
                }
                d_Sst[((size_t)ch * BATCH + b) * NS + i] = s;
                s = affine16r(p0, p1, p2, p3, v, s);
                v = vn; p0 = q0; p1 = q1; p2 = q2; p3 = q3; ++ch;
            }
        }
    }

    gsync(E0 + 4);

    // ---------------- P4b: outpass — out[t] = v_t + Pfx_s · s_j (r12) -------
    {
        u64 sj[NS];
        {
            const float4* s0 = reinterpret_cast<const float4*>(&d_Sst[((size_t)j * BATCH + b0) * NS]);
            const float4* s1 = reinterpret_cast<const float4*>(&d_Sst[((size_t)j * BATCH + b1) * NS]);
            float4 q0 = s0[0], q1 = s0[1], q2 = s0[2], q3 = s0[3];
            float4 r0 = s1[0], r1 = s1[1], r2 = s1[2], r3 = s1[3];
            sj[0]  = pack2(q0.x, r0.x); sj[1]  = pack2(q0.y, r0.y); sj[2]  = pack2(q0.z, r0.z); sj[3]  = pack2(q0.w, r0.w);
            sj[4]  = pack2(q1.x, r1.x); sj[5]  = pack2(q1.y, r1.y); sj[6]  = pack2(q1.z, r1.z); sj[7]  = pack2(q1.w, r1.w);
            sj[8]  = pack2(q2.x, r2.x); sj[9]  = pack2(q2.y, r2.y); sj[10] = pack2(q2.z, r2.z); sj[11] = pack2(q2.w, r2.w);
            sj[12] = pack2(q3.x, r3.x); sj[13] = pack2(q3.y, r3.y); sj[14] = pack2(q3.z, r3.z); sj[15] = pack2(q3.w, r3.w);
        }
        for (int s = 0; s < steps; ++s) {
            const int t = t0 + s;
            u64 v[NS];
            {
                const u64* vb = &d_Vt[((size_t)(j * LCH + s) * NS) * 128 + tid];
                #pragma unroll
                for (int q = 0; q < NS; ++q) v[q] = vb[q * 128];
            }
            const ulonglong2* P = reinterpret_cast<const ulonglong2*>(sPfx[s]);
            #pragma unroll
            for (int i = 0; i < NS; ++i) {
                u64 a = v[i];
                #pragma unroll
                for (int k = 0; k < 8; ++k) {
                    ulonglong2 p2v = P[i * 8 + k];
                    a = ffma2(p2v.x, sj[2 * k],     a);
                    a = ffma2(p2v.y, sj[2 * k + 1], a);
                }
                v[i] = a;
            }
            float lo[NS], hi[NS];
            #pragma unroll
            for (int q = 0; q < NS; ++q) unpk2(v[q], lo[q], hi[q]);
            float4* o0 = reinterpret_cast<float4*>(out + ((size_t)b0 * SEQ + t) * NS);
            float4* o1 = reinterpret_cast<float4*>(out + ((size_t)b1 * SEQ + t) * NS);
            o0[0] = make_float4(lo[0], lo[1], lo[2],  lo[3]);
            o0[1] = make_float4(lo[4], lo[5], lo[6],  lo[7]);
            o0[2] = make_float4(lo[8], lo[9], lo[10], lo[11]);
            o0[3] = make_float4(lo[12], lo[13], lo[14], lo[15]);
            o1[0] = make_float4(hi[0], hi[1], hi[2],  hi[3]);
            o1[1] = make_float4(hi[4], hi[5], hi[6],  hi[7]);
            o1[2] = make_float4(hi[8], hi[9], hi[10], hi[11]);
            o1[3] = make_float4(hi[12], hi[13], hi[14], hi[15]);
        }
    }
}

// =========================================================================
extern "C" void kernel_launch(void* const* d_in, const int* in_sizes, int n_in,
                              void* d_out, int out_size)
{
    (void)in_sizes; (void)n_in; (void)out_size;
    const float* obs = (const float*)d_in[0];
    const float* inp = (const float*)d_in[1];
    const float* A   = (const float*)d_in[2];
    const float* B   = (const float*)d_in[3];
    const float* C   = (const float*)d_in[4];
    const float* Q   = (const float*)d_in[5];
    const float* R   = (const float*)d_in[6];
    const float* x0  = (const float*)d_in[7];
    float* out = (float*)d_out;

    riccati_kernel<<<1, 256>>>(A, B, C, Q, R);
    fused_kernel<<<NCH, 128>>>(obs, inp, x0, out);
}

// round 17
// speedup vs baseline: 1.4775x; 1.4595x over previous
#include <cuda_runtime.h>
#include <cstdint>
#include <cstddef>

#define SEQ   4096
#define BATCH 256
#define NS    16
#define MS    8
#define US    4
#define LCH   8           // chunk length
#define NCH   512         // chunks
#define GRP   16          // chunks per group
#define NGRP  32          // groups
#define GQ    448         // gain scalars per t: M(256)|N(64)|K(128)

typedef unsigned long long u64;

// ---------------- device scratch ----------------
__device__ __align__(16) float2 d_G2[(size_t)SEQ * GQ];   // duplicated (g,g) pairs
__device__ int d_tlast;                                   // last distinct gain index
__device__ __align__(16) float d_Phi[NCH * 256];
__device__ __align__(16) float d_Psi[NGRP * 256];
__device__ __align__(16) float d_V  [(size_t)NCH  * BATCH * NS];
__device__ __align__(16) float d_GV [(size_t)NGRP * BATCH * NS];
__device__ __align__(16) float d_GS [(size_t)NGRP * BATCH * NS];
__device__ __align__(16) float d_Sst[(size_t)NCH  * BATCH * NS];
// packed per-step zero-start states v_t : [(chunk*LCH+step)*16+q][tid(128)] u64
__device__ __align__(16) u64 d_Vt[(size_t)NCH * LCH * NS * 128];

// ---------------- grid barrier (epoch-based, replay-safe) ----------------
__device__ unsigned int g_cnt = 0;
__device__ volatile unsigned int g_epoch = 0;

__device__ __forceinline__ void gsync(unsigned int target)
{
    __syncthreads();
    if (threadIdx.x == 0) {
        __threadfence();
        unsigned int prev = atomicAdd(&g_cnt, 1u);
        if (prev == gridDim.x - 1u) {
            atomicExch(&g_cnt, 0u);
            __threadfence();
            g_epoch = target;
        } else {
            while (g_epoch != target) __nanosleep(64);
        }
        __threadfence();
    }
    __syncthreads();
}

// ---------------- f32x2 helpers ----------------
__device__ __forceinline__ u64 ffma2(u64 a, u64 b, u64 c) {
    u64 d;
    asm("fma.rn.f32x2 %0, %1, %2, %3;" : "=l"(d) : "l"(a), "l"(b), "l"(c));
    return d;
}
__device__ __forceinline__ u64 fmul2(u64 a, u64 b) {
    u64 d;
    asm("mul.rn.f32x2 %0, %1, %2;" : "=l"(d) : "l"(a), "l"(b));
    return d;
}
__device__ __forceinline__ u64 pack2(float x, float y) {
    u64 r;
    asm("mov.b64 %0, {%1, %2};" : "=l"(r) : "f"(x), "f"(y));
    return r;
}
__device__ __forceinline__ void unpk2(u64 v, float& lo, float& hi) {
    asm("mov.b64 {%0, %1}, %2;" : "=f"(lo), "=f"(hi) : "l"(v));
}

// =========================================================================
// Kernel 1: serial Riccati recursion (one block)  [r12 verbatim]
// =========================================================================
__global__ void __launch_bounds__(256) riccati_kernel(
    const float* __restrict__ A, const float* __restrict__ B,
    const float* __restrict__ C, const float* __restrict__ Q,
    const float* __restrict__ R)
{
    __shared__ float sA[256], sB[64], sC[128], sQ[256], sR[64];
    __shared__ float sCA[128], sCB[32], sCQ[128], sSR0[64];
    __shared__ float sP[256], sT1[256], sPp[256], sCT[128], sW[128], sK[128], sSm[64], sSi[64];

    const int tid = threadIdx.x;
    const int i  = tid >> 4;
    const int jc = tid & 15;

    sA[tid] = A[tid];
    sQ[tid] = Q[tid];
    if (tid < 64)  { sB[tid] = B[tid]; sR[tid] = R[tid]; }
    if (tid < 128) sC[tid] = C[tid];
    sP[tid] = (i == jc) ? 1.0f : 0.0f;   // P0 = I
    __syncthreads();

    if (tid < 128) {                      // CA = C*A, CQ = C*Q  (8x16)
        float a = 0.f, q = 0.f;
        int m = tid >> 4, jj = tid & 15;
        #pragma unroll
        for (int k = 0; k < 16; ++k) {
            a += sC[m * 16 + k] * sA[k * 16 + jj];
            q += sC[m * 16 + k] * sQ[k * 16 + jj];
        }
        sCA[tid] = a; sCQ[tid] = q;
    }
    if (tid < 32) {                       // CB = C*B  (8x4)
        float a = 0.f;
        #pragma unroll
        for (int k = 0; k < 16; ++k) a += sC[(tid >> 2) * 16 + k] * sB[k * 4 + (tid & 3)];
        sCB[tid] = a;
    }
    __syncthreads();
    if (tid < 64) {                       // SR0 = CQ*C^T + R (8x8)
        int m = tid >> 3, n = tid & 7;
        float s = sR[tid];
        #pragma unroll
        for (int k = 0; k < 16; ++k) s += sCQ[m * 16 + k] * sC[n * 16 + k];
        sSR0[tid] = s;
    }
    __syncthreads();

    int tconv = SEQ;
    for (int t = 1; t < SEQ; ++t) {
        // (1) T1 = A * P
        float a = 0.f;
        #pragma unroll
        for (int k = 0; k < 16; ++k) a += sA[i * 16 + k] * sP[k * 16 + jc];
        sT1[tid] = a;
        __syncthreads();
        // (2) Ppri = T1*A^T + Q (all)  ;  CT = C*T1 (tid<128)
        a = sQ[tid];
        #pragma unroll
        for (int k = 0; k < 16; ++k) a += sT1[i * 16 + k] * sA[jc * 16 + k];
        sPp[tid] = a;
        if (tid < 128) {
            int m = tid >> 4, jj = tid & 15;
            float w = 0.f;
            #pragma unroll
            for (int k = 0; k < 16; ++k) w += sC[m * 16 + k] * sT1[k * 16 + jj];
            sCT[tid] = w;
        }
        __syncthreads();
        // (3) W = CT*A^T + CQ (tid<128)  ;  S = CT*CA^T + SR0 (tid 128..191)
        if (tid < 128) {
            int m = tid >> 4, jj = tid & 15;
            float w = sCQ[tid];
            #pragma unroll
            for (int k = 0; k < 16; ++k) w += sCT[m * 16 + k] * sA[jj * 16 + k];
            sW[tid] = w;
        } else if (tid < 192) {
            int q = tid - 128, m = q >> 3, n = q & 7;
            float s = sSR0[q];
            #pragma unroll
            for (int k = 0; k < 16; ++k) s += sCT[m * 16 + k] * sCA[n * 16 + k];
            sSm[q] = s;
        }
        __syncthreads();
        // (4) Sinv: warp-synchronous Gauss-Jordan (8 lanes, SPD)
        if (tid < 8) {
            float row[16];
            #pragma unroll
            for (int c = 0; c < 8; ++c) { row[c] = sSm[tid * 8 + c]; row[c + 8] = (c == tid) ? 1.f : 0.f; }
            #pragma unroll
            for (int p = 0; p < 8; ++p) {
                float pv  = __shfl_sync(0xFFu, row[p], p, 8);
                float f   = row[p];
                float inv = 1.0f / pv;
                #pragma unroll
                for (int c = 0; c < 16; ++c) {
                    float pr = __shfl_sync(0xFFu, row[c], p, 8) * inv;
                    row[c] = (tid == p) ? pr : (row[c] - f * pr);
                }
            }
            #pragma unroll
            for (int c = 0; c < 8; ++c) sSi[tid * 8 + c] = row[c + 8];
        }
        __syncthreads();
        // (5) K = W^T * Sinv  (16x8)
        if (tid < 128) {
            int ii = tid >> 3, m = tid & 7;
            float kk = 0.f;
            #pragma unroll
            for (int n = 0; n < 8; ++n) kk += sW[n * 16 + ii] * sSi[n * 8 + m];
            sK[tid] = kk;
        }
        __syncthreads();
        // (6) outputs + Ppost + convergence
        {
            float mm = sA[tid];                         // M = A - K*CA
            #pragma unroll
            for (int m = 0; m < 8; ++m) mm -= sK[i * 8 + m] * sCA[m * 16 + jc];
            d_G2[(size_t)t * GQ + tid] = make_float2(mm, mm);
        }
        if (tid < 64) {                                 // N = B - K*CB
            int ii = tid >> 2, u = tid & 3;
            float nn = sB[tid];
            #pragma unroll
            for (int m = 0; m < 8; ++m) nn -= sK[ii * 8 + m] * sCB[m * 4 + u];
            d_G2[(size_t)t * GQ + 256 + tid] = make_float2(nn, nn);
        }
        if (tid < 128) {
            float kk = sK[tid];
            d_G2[(size_t)t * GQ + 320 + tid] = make_float2(kk, kk);
        }
        float pn = sPp[tid];                            // Ppost = Ppri - K*W
        #pragma unroll
        for (int m = 0; m < 8; ++m) pn -= sK[i * 8 + m] * sW[m * 16 + jc];
        int pred = fabsf(pn - sP[tid]) < 1e-5f;
        sP[tid] = pn;
        int conv = __syncthreads_and(pred);
        if (conv) { tconv = t + 1; break; }
    }
    __syncthreads();
    if (tid == 0) d_tlast = (tconv < SEQ) ? (tconv - 1) : (SEQ - 1);
}

// =========================================================================
// merged affine step:  x <- M x + N u + K z  (single per-row accumulator,
// same FMA order as r12's compute_c + kstepm; c[] array eliminated)
// =========================================================================
__device__ __forceinline__ void kstep2(u64 x[NS], const u64* __restrict__ g,
                                       const u64 zz[MS], const u64 uu[US])
{
    u64 acc[NS];
    #pragma unroll
    for (int i = 0; i < NS; ++i) {
        const ulonglong2* gn = reinterpret_cast<const ulonglong2*>(g + 256 + i * 4);
        ulonglong2 n0 = gn[0], n1 = gn[1];
        u64 a = fmul2(n0.x, uu[0]);
        a = ffma2(n0.y, uu[1], a);
        a = ffma2(n1.x, uu[2], a);
        a = ffma2(n1.y, uu[3], a);
        const ulonglong2* gk = reinterpret_cast<const ulonglong2*>(g + 320 + i * 8);
        ulonglong2 k0 = gk[0], k1 = gk[1], k2 = gk[2], k3 = gk[3];
        a = ffma2(k0.x, zz[0], a); a = ffma2(k0.y, zz[1], a);
        a = ffma2(k1.x, zz[2], a); a = ffma2(k1.y, zz[3], a);
        a = ffma2(k2.x, zz[4], a); a = ffma2(k2.y, zz[5], a);
        a = ffma2(k3.x, zz[6], a); a = ffma2(k3.y, zz[7], a);
        const ulonglong2* gm = reinterpret_cast<const ulonglong2*>(g + i * 16);
        #pragma unroll
        for (int k = 0; k < 8; ++k) {
            ulonglong2 m2 = gm[k];
            a = ffma2(m2.x, x[2 * k],     a);
            a = ffma2(m2.y, x[2 * k + 1], a);
        }
        acc[i] = a;
    }
    #pragma unroll
    for (int i = 0; i < NS; ++i) x[i] = acc[i];
}

__device__ __forceinline__ void load_zu2(const float* __restrict__ obs,
                                         const float* __restrict__ inp,
                                         int b0, int b1, int t,
                                         u64 zz[MS], u64 uu[US])
{
    const float4* z0p = reinterpret_cast<const float4*>(obs + ((size_t)b0 * SEQ + t) * MS);
    const float4* z1p = reinterpret_cast<const float4*>(obs + ((size_t)b1 * SEQ + t) * MS);
    float4 a0 = __ldg(z0p), a1 = __ldg(z0p + 1);
    float4 c0 = __ldg(z1p), c1 = __ldg(z1p + 1);
    zz[0] = pack2(a0.x, c0.x); zz[1] = pack2(a0.y, c0.y);
    zz[2] = pack2(a0.z, c0.z); zz[3] = pack2(a0.w, c0.w);
    zz[4] = pack2(a1.x, c1.x); zz[5] = pack2(a1.y, c1.y);
    zz[6] = pack2(a1.z, c1.z); zz[7] = pack2(a1.w, c1.w);
    float4 u0 = __ldg(reinterpret_cast<const float4*>(inp + ((size_t)b0 * SEQ + t) * US));
    float4 u1 = __ldg(reinterpret_cast<const float4*>(inp + ((size_t)b1 * SEQ + t) * US));
    uu[0] = pack2(u0.x, u1.x); uu[1] = pack2(u0.y, u1.y);
    uu[2] = pack2(u0.z, u1.z); uu[3] = pack2(u0.w, u1.w);
}

// ---------------- 16-lane shuffle matvec with register-passed rows ----------
__device__ __forceinline__ float affine16r(float4 p0, float4 p1, float4 p2, float4 p3,
                                           float v, float s)
{
    float a = v;
    a += p0.x * __shfl_sync(0xFFFFFFFFu, s, 0, 16)  + p0.y * __shfl_sync(0xFFFFFFFFu, s, 1, 16)
       + p0.z * __shfl_sync(0xFFFFFFFFu, s, 2, 16)  + p0.w * __shfl_sync(0xFFFFFFFFu, s, 3, 16);
    a += p1.x * __shfl_sync(0xFFFFFFFFu, s, 4, 16)  + p1.y * __shfl_sync(0xFFFFFFFFu, s, 5, 16)
       + p1.z * __shfl_sync(0xFFFFFFFFu, s, 6, 16)  + p1.w * __shfl_sync(0xFFFFFFFFu, s, 7, 16);
    a += p2.x * __shfl_sync(0xFFFFFFFFu, s, 8, 16)  + p2.y * __shfl_sync(0xFFFFFFFFu, s, 9, 16)
       + p2.z * __shfl_sync(0xFFFFFFFFu, s, 10, 16) + p2.w * __shfl_sync(0xFFFFFFFFu, s, 11, 16);
    a += p3.x * __shfl_sync(0xFFFFFFFFu, s, 12, 16) + p3.y * __shfl_sync(0xFFFFFFFFu, s, 13, 16)
       + p3.z * __shfl_sync(0xFFFFFFFFu, s, 14, 16) + p3.w * __shfl_sync(0xFFFFFFFFu, s, 15, 16);
    return a;
}

// =========================================================================
// Kernel 2: fused persistent kernel [r12 structure; vpass uses merged kstep2]
// =========================================================================
__global__ void __launch_bounds__(128, 4) fused_kernel(
    const float* __restrict__ obs, const float* __restrict__ inp,
    const float* __restrict__ x0, float* __restrict__ out)
{
    __shared__ __align__(16) u64 sG[LCH][GQ];      // 28672 B gains (dup pairs)
    __shared__ __align__(16) u64 sPfx[LCH][256];   // 16384 B prefix matrices (dup pairs)
    __shared__ float sPh[2][256];                  // 2048 B psi ping-pong

    const int j   = blockIdx.x;
    const int tid = threadIdx.x;
    const int b0  = tid, b1 = tid + 128;
    const int t0  = j * LCH + 1;
    const int steps = (t0 + LCH <= SEQ) ? LCH : (SEQ - t0);

    const unsigned int E0 = g_epoch;     // per-thread; epoch can't advance
    const int tlast = d_tlast;           // until all blocks reach first gsync

    // ---------------- P1a: stage all LCH gain sets (clamped index) ----------
    #pragma unroll
    for (int s = 0; s < LCH; ++s) {
        int tt = t0 + s; if (tt > tlast) tt = tlast;
        const float4* src = reinterpret_cast<const float4*>(&d_G2[(size_t)tt * GQ]);
        reinterpret_cast<float4*>(sG[s])[tid] = __ldg(src + tid);      // prior launch — __ldg legal
        if (tid < 96) reinterpret_cast<float4*>(sG[s])[128 + tid] = __ldg(src + 128 + tid);
    }
    __syncthreads();

    // ---------------- P1b: prefix matrices Pfx_s = M_s ··· M_0 --------------
    {
        sPfx[0][tid]       = sG[0][tid];
        sPfx[0][tid + 128] = sG[0][tid + 128];
        __syncthreads();
        for (int s = 1; s < steps; ++s) {
            const float* Ms = reinterpret_cast<const float*>(sG[s]);
            const float* Pp = reinterpret_cast<const float*>(sPfx[s - 1]);
            #pragma unroll
            for (int h = 0; h < 2; ++h) {
                int e = tid + h * 128, ii = e >> 4, jc = e & 15;
                float a = 0.f;
                #pragma unroll
                for (int k = 0; k < 16; ++k) a += Ms[2 * (ii * 16 + k)] * Pp[2 * (k * 16 + jc)];
                sPfx[s][e] = pack2(a, a);
            }
            __syncthreads();
        }
        const float* Pl = reinterpret_cast<const float*>(sPfx[steps - 1]);
        d_Phi[j * 256 + tid]       = Pl[2 * tid];
        d_Phi[j * 256 + tid + 128] = Pl[2 * (tid + 128)];
    }

    // ---------------- P1c: vpass; store per-step v_t packed -----------------
    {
        u64 x[NS];
        #pragma unroll
        for (int q = 0; q < NS; ++q) x[q] = 0ull;
        for (int s = 0; s < steps; ++s) {
            u64 zz[MS], uu[US];
            load_zu2(obs, inp, b0, b1, t0 + s, zz, uu);
            kstep2(x, sG[s], zz, uu);
            u64* vb = &d_Vt[((size_t)(j * LCH + s) * NS) * 128 + tid];
            #pragma unroll
            for (int q = 0; q < NS; ++q) vb[q * 128] = x[q];
        }
        float lo[NS], hi[NS];
        #pragma unroll
        for (int q = 0; q < NS; ++q) unpk2(x[q], lo[q], hi[q]);
        float4* v0 = reinterpret_cast<float4*>(&d_V[((size_t)j * BATCH + b0) * NS]);
        float4* v1 = reinterpret_cast<float4*>(&d_V[((size_t)j * BATCH + b1) * NS]);
        v0[0] = make_float4(lo[0], lo[1], lo[2],  lo[3]);
        v0[1] = make_float4(lo[4], lo[5], lo[6],  lo[7]);
        v0[2] = make_float4(lo[8], lo[9], lo[10], lo[11]);
        v0[3] = make_float4(lo[12], lo[13], lo[14], lo[15]);
        v1[0] = make_float4(hi[0], hi[1], hi[2],  hi[3]);
        v1[1] = make_float4(hi[4], hi[5], hi[6],  hi[7]);
        v1[2] = make_float4(hi[8], hi[9], hi[10], hi[11]);
        v1[3] = make_float4(hi[12], hi[13], hi[14], hi[15]);
    }
    if (j == 0) {       // out[b][0] = x0 for every batch
        const float4* xp = reinterpret_cast<const float4*>(x0);
        float4 x00 = __ldg(xp), x01 = __ldg(xp + 1), x02 = __ldg(xp + 2), x03 = __ldg(xp + 3);
        float4* o0 = reinterpret_cast<float4*>(out + (size_t)b0 * SEQ * NS);
        float4* o1 = reinterpret_cast<float4*>(out + (size_t)b1 * SEQ * NS);
        o0[0] = x00; o0[1] = x01; o0[2] = x02; o0[3] = x03;
        o1[0] = x00; o1[1] = x01; o1[2] = x02; o1[3] = x03;
    }

    gsync(E0 + 1);

    // ---------------- P2: psi (blocks 480..511 only) | gscanA (0..479) ------
    if (j >= NCH - NGRP) {
        const int g = j - (NCH - NGRP);
        sPh[0][tid]       = d_Phi[(g * GRP) * 256 + tid];
        sPh[0][tid + 128] = d_Phi[(g * GRP) * 256 + tid + 128];
        __syncthreads();
        int pp = 0;
        for (int c = 1; c < GRP; ++c) {
            const float* Ms = &d_Phi[(g * GRP + c) * 256];
            #pragma unroll
            for (int h = 0; h < 2; ++h) {
                int e = tid + h * 128, ii = e >> 4, jc = e & 15;
                float a = 0.f;
                #pragma unroll
                for (int k = 0; k < 16; ++k) a += Ms[ii * 16 + k] * sPh[pp][k * 16 + jc];
                sPh[pp ^ 1][e] = a;
            }
            __syncthreads();
            pp ^= 1;
        }
        d_Psi[g * 256 + tid]       = sPh[pp][tid];
        d_Psi[g * 256 + tid + 128] = sPh[pp][tid + 128];
    } else {
        const int i = tid & 15;
        const int ntask = (j < 64) ? 3 : 2;
        for (int r = 0; r < ntask; ++r) {
            const int T = (r == 0) ? j : ((r == 1) ? j + (NCH - NGRP) : 2 * (NCH - NGRP) + j);
            const int g = T >> 5, sub = T & 31;
            const int b = sub * 8 + (tid >> 4);
            float s = 0.f;
            int ch = g * GRP;
            float v = d_V[((size_t)ch * BATCH + b) * NS + i];
            const float4* pr = reinterpret_cast<const float4*>(&d_Phi[ch * 256 + i * 16]);
            float4 p0 = pr[0], p1 = pr[1], p2 = pr[2], p3 = pr[3];
            #pragma unroll
            for (int c = 0; c < GRP; ++c) {
                float vn = 0.f; float4 q0, q1, q2, q3;
                if (c < GRP - 1) {                              // prefetch next chunk
                    const int chn = ch + 1;
                    vn = d_V[((size_t)chn * BATCH + b) * NS + i];
                    const float4* qn = reinterpret_cast<const float4*>(&d_Phi[chn * 256 + i * 16]);
                    q0 = qn[0]; q1 = qn[1]; q2 = qn[2]; q3 = qn[3];
                }
                s = affine16r(p0, p1, p2, p3, v, s);
                v = vn; p0 = q0; p1 = q1; p2 = q2; p3 = q3; ++ch;
            }
            d_GV[((size_t)g * BATCH + b) * NS + i] = s;
        }
    }

    gsync(E0 + 2);

    // ---------------- P3: gscanB (blocks 0..31, serial over 32 groups) ------
    if (j < 32) {
        const int b = j * 8 + (tid >> 4);
        const int i = tid & 15;
        float s = __ldg(x0 + i);
        float v = d_GV[(size_t)b * NS + i];
        const float4* pr = reinterpret_cast<const float4*>(&d_Psi[i * 16]);
        float4 p0 = pr[0], p1 = pr[1], p2 = pr[2], p3 = pr[3];
        #pragma unroll
        for (int g = 0; g < NGRP; ++g) {
            float vn = 0.f; float4 q0, q1, q2, q3;
            if (g < NGRP - 1) {                                 // prefetch next group
                vn = d_GV[((size_t)(g + 1) * BATCH + b) * NS + i];
                const float4* qn = reinterpret_cast<const float4*>(&d_Psi[(g + 1) * 256 + i * 16]);
                q0 = qn[0]; q1 = qn[1]; q2 = qn[2]; q3 = qn[3];
            }
            d_GS[((size_t)g * BATCH + b) * NS + i] = s;
            s = affine16r(p0, p1, p2, p3, v, s);
            v = vn; p0 = q0; p1 = q1; p2 = q2; p3 = q3;
        }
    }

    gsync(E0 + 3);

    // ---------------- P4a: gscanC (all blocks, 2 tasks, prefetched) ---------
    {
        const int i = tid & 15;
        #pragma unroll
        for (int rep = 0; rep < 2; ++rep) {
            const int T = j + rep * NCH;
            const int g = T >> 5, sub = T & 31;
            const int b = sub * 8 + (tid >> 4);
            float s = d_GS[((size_t)g * BATCH + b) * NS + i];
            int ch = g * GRP;
            float v = d_V[((size_t)ch * BATCH + b) * NS + i];
            const float4* pr = reinterpret_cast<const float4*>(&d_Phi[ch * 256 + i * 16]);
            float4 p0 = pr[0], p1 = pr[1], p2 = pr[2], p3 = pr[3];
            #pragma unroll
            for (int c = 0; c < GRP; ++c) {
                float vn = 0.f; float4 q0, q1, q2, q3;
                if (c < GRP - 1) {
                    const int chn = ch + 1;
                    vn = d_V[((size_t)chn * BATCH + b) * NS + i];
                    const float4* qn = reinterpret_cast<const float4*>(&d_Phi[chn * 256 + i * 16]);
                    q0 = qn[0]; q1 = qn[1]; q2 = qn[2]; q3 = qn[3];
                }
                d_Sst[((size_t)ch * BATCH + b) * NS + i] = s;
                s = affine16r(p0, p1, p2, p3, v, s);
                v = vn; p0 = q0; p1 = q1; p2 = q2; p3 = q3; ++ch;
            }
        }
    }

    gsync(E0 + 4);

    // ---------------- P4b: outpass — out[t] = v_t + Pfx_s · s_j -------------
    {
        u64 sj[NS];
        {
            const float4* s0 = reinterpret_cast<const float4*>(&d_Sst[((size_t)j * BATCH + b0) * NS]);
            const float4* s1 = reinterpret_cast<const float4*>(&d_Sst[((size_t)j * BATCH + b1) * NS]);
            float4 q0 = s0[0], q1 = s0[1], q2 = s0[2], q3 = s0[3];
            float4 r0 = s1[0], r1 = s1[1], r2 = s1[2], r3 = s1[3];
            sj[0]  = pack2(q0.x, r0.x); sj[1]  = pack2(q0.y, r0.y); sj[2]  = pack2(q0.z, r0.z); sj[3]  = pack2(q0.w, r0.w);
            sj[4]  = pack2(q1.x, r1.x); sj[5]  = pack2(q1.y, r1.y); sj[6]  = pack2(q1.z, r1.z); sj[7]  = pack2(q1.w, r1.w);
            sj[8]  = pack2(q2.x, r2.x); sj[9]  = pack2(q2.y, r2.y); sj[10] = pack2(q2.z, r2.z); sj[11] = pack2(q2.w, r2.w);
            sj[12] = pack2(q3.x, r3.x); sj[13] = pack2(q3.y, r3.y); sj[14] = pack2(q3.z, r3.z); sj[15] = pack2(q3.w, r3.w);
        }
        for (int s = 0; s < steps; ++s) {
            const int t = t0 + s;
            u64 v[NS];
            {
                const u64* vb = &d_Vt[((size_t)(j * LCH + s) * NS) * 128 + tid];
                #pragma unroll
                for (int q = 0; q < NS; ++q) v[q] = vb[q * 128];
            }
            const ulonglong2* P = reinterpret_cast<const ulonglong2*>(sPfx[s]);
            #pragma unroll
            for (int i = 0; i < NS; ++i) {
                u64 a = v[i];
                #pragma unroll
                for (int k = 0; k < 8; ++k) {
                    ulonglong2 p2v = P[i * 8 + k];
                    a = ffma2(p2v.x, sj[2 * k],     a);
                    a = ffma2(p2v.y, sj[2 * k + 1], a);
                }
                v[i] = a;
            }
            float lo[NS], hi[NS];
            #pragma unroll
            for (int q = 0; q < NS; ++q) unpk2(v[q], lo[q], hi[q]);
            float4* o0 = reinterpret_cast<float4*>(out + ((size_t)b0 * SEQ + t) * NS);
            float4* o1 = reinterpret_cast<float4*>(out + ((size_t)b1 * SEQ + t) * NS);
            o0[0] = make_float4(lo[0], lo[1], lo[2],  lo[3]);
            o0[1] = make_float4(lo[4], lo[5], lo[6],  lo[7]);
            o0[2] = make_float4(lo[8], lo[9], lo[10], lo[11]);
            o0[3] = make_float4(lo[12], lo[13], lo[14], lo[15]);
            o1[0] = make_float4(hi[0], hi[1], hi[2],  hi[3]);
            o1[1] = make_float4(hi[4], hi[5], hi[6],  hi[7]);
            o1[2] = make_float4(hi[8], hi[9], hi[10], hi[11]);
            o1[3] = make_float4(hi[12], hi[13], hi[14], hi[15]);
        }
    }
}

// =========================================================================
extern "C" void kernel_launch(void* const* d_in, const int* in_sizes, int n_in,
                              void* d_out, int out_size)
{
    (void)in_sizes; (void)n_in; (void)out_size;
    const float* obs = (const float*)d_in[0];
    const float* inp = (const float*)d_in[1];
    const float* A   = (const float*)d_in[2];
    const float* B   = (const float*)d_in[3];
    const float* C   = (const float*)d_in[4];
    const float* Q   = (const float*)d_in[5];
    const float* R   = (const float*)d_in[6];
    const float* x0  = (const float*)d_in[7];
    float* out = (float*)d_out;

    riccati_kernel<<<1, 256>>>(A, B, C, Q, R);
    fused_kernel<<<NCH, 128>>>(obs, inp, x0, out);
}